// round 1
// baseline (speedup 1.0000x reference)
#include <cuda_runtime.h>

#define TT 4096
#define BB 128
#define CC 46
#define LL 43
#define CHUNKS 32           /* TT / 128 */
#define NEGF (-1e30f)

// ---------------- scratch (static device globals; no allocation) ----------------
__device__ float  g_w0[CC];            // exp(weights) for S0 sum (incl. s_O at c=1)
__device__ float  g_w1[CC];            // exp(weights) for S1 sum
__device__ float  g_sc[4];             // [0]=s_0I, [1]=s_1I, [2]=s_fin
__device__ float4 g_cmats[BB * CHUNKS];  // per-(batch,chunk) semiring product
__device__ float  g_numpart[BB * CHUNKS];
__device__ float  g_res[BB];

// ---------------- semiring helpers ----------------
__device__ __forceinline__ float lse2f(float x, float y) {
    float mx = fmaxf(x, y);
    float mn = fminf(x, y);
    return mx + __logf(1.0f + __expf(mn - mx));
}

// C = A (later) ⊗ B (earlier) in (logsumexp,+) semiring. layout x=00,y=01,z=10,w=11
__device__ __forceinline__ float4 semimul(const float4 A, const float4 B) {
    float4 C;
    C.x = lse2f(A.x + B.x, A.y + B.z);
    C.y = lse2f(A.x + B.y, A.y + B.w);
    C.z = lse2f(A.z + B.x, A.w + B.z);
    C.w = lse2f(A.z + B.y, A.w + B.w);
    return C;
}

// ---------------- k0: den_params -> softmax weights (tiny, 1 thread) ----------------
__global__ void k0_params(const float* __restrict__ dp) {
    if (threadIdx.x != 0) return;
    // log_softmax over dp[0..45]  (g0)
    float m0 = dp[0];
#pragma unroll
    for (int i = 1; i < CC; i++) m0 = fmaxf(m0, dp[i]);
    float s0 = 0.f;
#pragma unroll
    for (int i = 0; i < CC; i++) s0 += __expf(dp[i] - m0);
    float lz0 = m0 + __logf(s0);
    // log_softmax over dp[46..89] (g1, L+1 = 44 entries)
    float m1 = dp[CC];
#pragma unroll
    for (int i = 1; i < LL + 1; i++) m1 = fmaxf(m1, dp[CC + i]);
    float s1 = 0.f;
#pragma unroll
    for (int i = 0; i < LL + 1; i++) s1 += __expf(dp[CC + i] - m1);
    float lz1 = m1 + __logf(s1);

    g_w0[0] = 0.f; g_w0[2] = 0.f;
    g_w1[0] = 0.f; g_w1[1] = 0.f; g_w1[2] = 0.f;
    g_w0[1] = __expf(dp[0] - lz0);                 // exp(s_O), folds s_O+lp[1] into S0
#pragma unroll
    for (int c = 3; c < CC; c++) {
        g_w0[c] = __expf(dp[c - 2] - lz0);         // exp(s0_lab[c-3]) = exp(g0[c-2])
        g_w1[c] = __expf(dp[CC + (c - 2)] - lz1);  // exp(s1_lab[c-3]) = exp(g1[c-2])
    }
    g_sc[0] = dp[LL + 1] - lz0;   // s_0I = g0[44]
    g_sc[1] = dp[CC]     - lz1;   // s_1I = g1[0]
    g_sc[2] = dp[LL + 2] - lz0;   // s_fin = g0[45]
}

// ---------------- k1: main streaming kernel ----------------
// grid (TT/128, BB), block 128 threads, thread = one timestep.
__global__ void __launch_bounds__(128) k1_main(
    const float* __restrict__ lp,
    const int* __restrict__ lens,
    const int* __restrict__ labels)
{
    __shared__ float  tile[128 * CC];     // 23552 B, 184 B per timestep row
    __shared__ float  w0s[CC], w1s[CC];
    __shared__ float4 msm[128];
    __shared__ float  red[4];

    const int tid = threadIdx.x;
    const int b   = blockIdx.y;
    const int tb  = blockIdx.x * 128;

    if (tid < CC) { w0s[tid] = g_w0[tid]; w1s[tid] = g_w1[tid]; }

    // coalesced float4 staging of 128 rows x 46 floats = 1472 float4 (16B-aligned base)
    const float4* __restrict__ src = (const float4*)(lp + ((size_t)b * TT + tb) * CC);
    float4* dst = (float4*)tile;
#pragma unroll
    for (int i = 0; i < 11; i++) dst[tid + i * 128] = src[tid + i * 128];
    {
        int i = tid + 11 * 128;
        if (i < 1472) dst[i] = src[i];
    }
    __syncthreads();

    // per-thread row read: 23 float2 LDS, stride 46 floats -> conflict-free
    float v[CC];
    const float2* r2 = (const float2*)(tile + tid * CC);
#pragma unroll
    for (int i = 0; i < 23; i++) { float2 q = r2[i]; v[2 * i] = q.x; v[2 * i + 1] = q.y; }

    // shared max over weighted columns {1, 3..45}
    float m = v[1];
#pragma unroll
    for (int c = 3; c < CC; c++) m = fmaxf(m, v[c]);

    // one exp per column, two weighted sums
    float S0 = __expf(v[1] - m) * w0s[1];
    float S1 = 0.f;
#pragma unroll
    for (int c = 3; c < CC; c++) {
        float e = __expf(v[c] - m);
        S0 = fmaf(e, w0s[c], S0);
        S1 = fmaf(e, w1s[c], S1);
    }

    const float M00 = m + __logf(S0);   // LSE(s_O+lp1, s0_lab+lp_lab)
    const float M01 = m + __logf(S1);   // LSE(s1_lab+lp_lab)
    const float lp2 = v[2];
    const float M10 = g_sc[0] + lp2;    // s_0I + lp2
    const float M11 = g_sc[1] + lp2;    // s_1I + lp2

    const int  t     = tb + tid;
    const bool valid = t < lens[b];
    const int  lab   = labels[(size_t)b * TT + t];
    const float tok  = valid ? tile[tid * CC + lab] : 0.f;

    float4 M = valid ? make_float4(M00, M01, M10, M11)
                     : make_float4(0.f, NEGF, NEGF, 0.f);   // semiring identity
    msm[tid] = M;

    // block-reduce masked token logprob (commutative sum)
    float s = tok;
#pragma unroll
    for (int o = 16; o > 0; o >>= 1) s += __shfl_xor_sync(0xffffffffu, s, o);
    if ((tid & 31) == 0) red[tid >> 5] = s;
    __syncthreads();
    if (tid == 0) g_numpart[b * CHUNKS + blockIdx.x] = red[0] + red[1] + red[2] + red[3];

    // ordered semiring tree reduce over the 128 timestep matrices (later ⊗ earlier)
#pragma unroll
    for (int st = 1; st < 128; st <<= 1) {
        bool act = (tid & (2 * st - 1)) == 0;
        float4 r;
        if (act) r = semimul(msm[tid + st], msm[tid]);
        __syncthreads();
        if (act) msm[tid] = r;
        __syncthreads();
    }
    if (tid == 0) g_cmats[b * CHUNKS + blockIdx.x] = msm[0];
}

// ---------------- k2: per-batch chunk reduction ----------------
__global__ void __launch_bounds__(32) k2_batch() {
    const int b = blockIdx.x, tid = threadIdx.x;
    __shared__ float4 sm[CHUNKS];
    sm[tid] = g_cmats[b * CHUNKS + tid];
    float np = g_numpart[b * CHUNKS + tid];
    __syncwarp();
#pragma unroll
    for (int st = 1; st < CHUNKS; st <<= 1) {
        bool act = (tid & (2 * st - 1)) == 0;
        float4 r;
        if (act) r = semimul(sm[tid + st], sm[tid]);
        __syncwarp();
        if (act) sm[tid] = r;
        __syncwarp();
    }
    // num = sum of partials
#pragma unroll
    for (int o = 16; o > 0; o >>= 1) np += __shfl_xor_sync(0xffffffffu, np, o);
    if (tid == 0) {
        float4 P = sm[0];
        // alpha0 = [0, NEG]; den = LSE(P00+0, P01+NEG) + s_fin
        float a0  = lse2f(P.x, P.y + NEGF);
        float den = a0 + g_sc[2];
        g_res[b] = np - den;
    }
}

// ---------------- k3: final sum over batches ----------------
__global__ void __launch_bounds__(128) k3_final(float* __restrict__ out) {
    const int tid = threadIdx.x;
    float vsum = g_res[tid];
#pragma unroll
    for (int o = 16; o > 0; o >>= 1) vsum += __shfl_xor_sync(0xffffffffu, vsum, o);
    __shared__ float r[4];
    if ((tid & 31) == 0) r[tid >> 5] = vsum;
    __syncthreads();
    if (tid == 0) out[0] = r[0] + r[1] + r[2] + r[3];
}

// ---------------- launcher ----------------
extern "C" void kernel_launch(void* const* d_in, const int* in_sizes, int n_in,
                              void* d_out, int out_size) {
    const float* lp     = (const float*)d_in[0];  // (B,T,C) float32
    const float* dp     = (const float*)d_in[1];  // (2L+4,) float32
    const int*   lens   = (const int*)d_in[2];    // (B,) int32
    const int*   labels = (const int*)d_in[3];    // (B,T) int32

    k0_params<<<1, 32>>>(dp);
    dim3 grid(TT / 128, BB);
    k1_main<<<grid, 128>>>(lp, lens, labels);
    k2_batch<<<BB, 32>>>();
    k3_final<<<1, 128>>>((float*)d_out);
}

// round 2
// speedup vs baseline: 1.0759x; 1.0759x over previous
#include <cuda_runtime.h>

#define TT 4096
#define BB 128
#define CC 46
#define LL 43
#define CHUNKS 32           /* TT / 128 */
#define NEGF (-1e30f)
#define NINF (-3.4e38f)

// ---------------- scratch (static device globals; no allocation) ----------------
__device__ float4 g_cmats[BB * CHUNKS];   // per-(batch,chunk) semiring product
__device__ float  g_numpart[BB * CHUNKS];

// ---------------- semiring helpers ----------------
__device__ __forceinline__ float lse2f(float x, float y) {
    float mx = fmaxf(x, y);
    float mn = fminf(x, y);
    return mx + __logf(1.0f + __expf(mn - mx));
}

// C = A (later) (x) B (earlier) in (logsumexp,+) semiring. x=00,y=01,z=10,w=11
__device__ __forceinline__ float4 semimul(const float4 A, const float4 B) {
    float4 C;
    C.x = lse2f(A.x + B.x, A.y + B.z);
    C.y = lse2f(A.x + B.y, A.y + B.w);
    C.z = lse2f(A.z + B.x, A.w + B.z);
    C.w = lse2f(A.z + B.y, A.w + B.w);
    return C;
}

__device__ __forceinline__ float4 shfl_down4(float4 v, int s, int w) {
    float4 r;
    r.x = __shfl_down_sync(0xffffffffu, v.x, s, w);
    r.y = __shfl_down_sync(0xffffffffu, v.y, s, w);
    r.z = __shfl_down_sync(0xffffffffu, v.z, s, w);
    r.w = __shfl_down_sync(0xffffffffu, v.w, s, w);
    return r;
}

// ---------------- k1: main streaming kernel (params fused in) ----------------
// grid (TT/128, BB), block 128 threads, thread = one timestep.
__global__ void __launch_bounds__(128) k1_main(
    const float* __restrict__ lp,
    const float* __restrict__ dp,
    const int* __restrict__ lens,
    const int* __restrict__ labels)
{
    __shared__ float  tile[128 * CC];     // 23552 B, 184 B per timestep row
    __shared__ float  w0s[CC], w1s[CC];
    __shared__ float  scs[2];             // [0]=s_0I, [1]=s_1I
    __shared__ float4 warpM[4];
    __shared__ float  warpT[4];

    const int tid  = threadIdx.x;
    const int lane = tid & 31;
    const int wid  = tid >> 5;
    const int b    = blockIdx.y;
    const int tb   = blockIdx.x * 128;

    // --- warp 0: recompute softmax weights from den_params (L2 broadcast) ---
    if (wid == 0) {
        // g0 over dp[0..45]
        float a = dp[lane];
        float bb = (lane + 32 < CC) ? dp[lane + 32] : NINF;
        float m = fmaxf(a, bb);
#pragma unroll
        for (int o = 16; o; o >>= 1) m = fmaxf(m, __shfl_xor_sync(0xffffffffu, m, o));
        float s = __expf(a - m) + __expf(bb - m);
#pragma unroll
        for (int o = 16; o; o >>= 1) s += __shfl_xor_sync(0xffffffffu, s, o);
        const float lz0 = m + __logf(s);
        // g1 over dp[46..89]  (44 entries)
        float a1 = (lane < LL + 1) ? dp[CC + lane] : NINF;
        float b1 = (lane + 32 < LL + 1) ? dp[CC + lane + 32] : NINF;
        float m1 = fmaxf(a1, b1);
#pragma unroll
        for (int o = 16; o; o >>= 1) m1 = fmaxf(m1, __shfl_xor_sync(0xffffffffu, m1, o));
        float s1 = __expf(a1 - m1) + __expf(b1 - m1);
#pragma unroll
        for (int o = 16; o; o >>= 1) s1 += __shfl_xor_sync(0xffffffffu, s1, o);
        const float lz1 = m1 + __logf(s1);

#pragma unroll
        for (int c = lane; c < CC; c += 32) {
            float w0 = 0.f, w1 = 0.f;
            if (c == 1) w0 = __expf(dp[0] - lz0);            // exp(s_O) folded into S0
            if (c >= 3) {
                w0 = __expf(dp[c - 2] - lz0);                // exp(s0_lab[c-3])
                w1 = __expf(dp[CC + c - 2] - lz1);           // exp(s1_lab[c-3])
            }
            w0s[c] = w0; w1s[c] = w1;
        }
        if (lane == 0) {
            scs[0] = dp[LL + 1] - lz0;   // s_0I
            scs[1] = dp[CC] - lz1;       // s_1I
        }
    }

    // --- coalesced float4 staging: 128 rows x 46 floats = 1472 float4 ---
    const float4* __restrict__ src = (const float4*)(lp + ((size_t)b * TT + tb) * CC);
    float4* dst = (float4*)tile;
#pragma unroll
    for (int i = 0; i < 11; i++) dst[tid + i * 128] = src[tid + i * 128];
    {
        int i = tid + 11 * 128;
        if (i < 1472) dst[i] = src[i];
    }
    __syncthreads();

    // per-thread row: 23 float2 LDS, stride 46 floats -> conflict-free
    float v[CC];
    const float2* r2 = (const float2*)(tile + tid * CC);
#pragma unroll
    for (int i = 0; i < 23; i++) { float2 q = r2[i]; v[2 * i] = q.x; v[2 * i + 1] = q.y; }

    // shared max over weighted columns {1, 3..45}
    float m = v[1];
#pragma unroll
    for (int c = 3; c < CC; c++) m = fmaxf(m, v[c]);

    // one exp per column, two weighted sums
    float S0 = __expf(v[1] - m) * w0s[1];
    float S1 = 0.f;
#pragma unroll
    for (int c = 3; c < CC; c++) {
        float e = __expf(v[c] - m);
        S0 = fmaf(e, w0s[c], S0);
        S1 = fmaf(e, w1s[c], S1);
    }

    const float M00 = m + __logf(S0);
    const float M01 = m + __logf(S1);
    const float lp2 = v[2];
    const float M10 = scs[0] + lp2;
    const float M11 = scs[1] + lp2;

    const int  t     = tb + tid;
    const bool valid = t < lens[b];
    const int  lab   = labels[(size_t)b * TT + t];
    float tok        = valid ? tile[tid * CC + lab] : 0.f;

    float4 M = valid ? make_float4(M00, M01, M10, M11)
                     : make_float4(0.f, NEGF, NEGF, 0.f);   // semiring identity

    // --- warp-level ordered semiring tree (later (x) earlier) ---
#pragma unroll
    for (int s = 1; s < 32; s <<= 1) {
        float4 o4 = shfl_down4(M, s, 32);
        if ((lane & (2 * s - 1)) == 0) M = semimul(o4, M);
    }
    // masked token-logprob warp sum
#pragma unroll
    for (int o = 16; o; o >>= 1) tok += __shfl_xor_sync(0xffffffffu, tok, o);

    if (lane == 0) { warpM[wid] = M; warpT[wid] = tok; }
    __syncthreads();

    if (wid == 0) {
        float4 W = (lane < 4) ? warpM[lane] : make_float4(0.f, NEGF, NEGF, 0.f);
        float  T = (lane < 4) ? warpT[lane] : 0.f;
#pragma unroll
        for (int s = 1; s < 4; s <<= 1) {
            float4 o4 = shfl_down4(W, s, 32);
            if ((lane & (2 * s - 1)) == 0 && lane + s < 4) W = semimul(o4, W);
        }
#pragma unroll
        for (int o = 16; o; o >>= 1) T += __shfl_xor_sync(0xffffffffu, T, o);
        if (lane == 0) {
            g_cmats[b * CHUNKS + blockIdx.x]   = W;
            g_numpart[b * CHUNKS + blockIdx.x] = T;
        }
    }
}

// ---------------- k2_final: chunk reduce + den + num + global sum ----------------
// one block, 1024 threads; 8 lanes per batch (128 batches).
__global__ void __launch_bounds__(1024) k2_final(
    const float* __restrict__ dp, float* __restrict__ out)
{
    const int tid  = threadIdx.x;
    const int lane = tid & 31;
    const int wid  = tid >> 5;
    __shared__ float s_fin_sh;
    __shared__ float resv[BB];
    __shared__ float red[32];

    // warp 0: recompute lz0 -> s_fin
    if (wid == 0) {
        float a = dp[lane];
        float bb = (lane + 32 < CC) ? dp[lane + 32] : NINF;
        float m = fmaxf(a, bb);
#pragma unroll
        for (int o = 16; o; o >>= 1) m = fmaxf(m, __shfl_xor_sync(0xffffffffu, m, o));
        float s = __expf(a - m) + __expf(bb - m);
#pragma unroll
        for (int o = 16; o; o >>= 1) s += __shfl_xor_sync(0xffffffffu, s, o);
        if (lane == 0) s_fin_sh = dp[LL + 2] - (m + __logf(s));
    }

    // 8 lanes per batch, each folds 4 consecutive chunks (ordered)
    const int b = tid >> 3;
    const int g = tid & 7;
    const float4* cm = g_cmats + b * CHUNKS + g * 4;
    const float*  np4 = g_numpart + b * CHUNKS + g * 4;
    float4 M = cm[0];
    M = semimul(cm[1], M);
    M = semimul(cm[2], M);
    M = semimul(cm[3], M);
    float np = np4[0] + np4[1] + np4[2] + np4[3];

    // width-8 shuffle trees
#pragma unroll
    for (int s = 1; s < 8; s <<= 1) {
        float4 o4 = shfl_down4(M, s, 8);
        if ((g & (2 * s - 1)) == 0) M = semimul(o4, M);
    }
#pragma unroll
    for (int s = 4; s; s >>= 1) np += __shfl_down_sync(0xffffffffu, np, s, 8);

    __syncthreads();   // s_fin_sh visible
    if (g == 0) {
        float den = lse2f(M.x, M.y + NEGF) + s_fin_sh;   // alpha0=[0,NEG]
        resv[b] = np - den;
    }
    __syncthreads();

    float v = (tid < BB) ? resv[tid] : 0.f;
#pragma unroll
    for (int o = 16; o; o >>= 1) v += __shfl_xor_sync(0xffffffffu, v, o);
    if (lane == 0) red[wid] = v;
    __syncthreads();
    if (tid == 0) {
        float t = 0.f;
#pragma unroll
        for (int i = 0; i < 32; i++) t += red[i];
        out[0] = t;
    }
}

// ---------------- launcher ----------------
extern "C" void kernel_launch(void* const* d_in, const int* in_sizes, int n_in,
                              void* d_out, int out_size) {
    const float* lp     = (const float*)d_in[0];  // (B,T,C) float32
    const float* dp     = (const float*)d_in[1];  // (2L+4,) float32
    const int*   lens   = (const int*)d_in[2];    // (B,) int32
    const int*   labels = (const int*)d_in[3];    // (B,T) int32

    dim3 grid(TT / 128, BB);
    k1_main<<<grid, 128>>>(lp, dp, lens, labels);
    k2_final<<<1, 1024>>>(dp, (float*)d_out);
}